// round 9
// baseline (speedup 1.0000x reference)
#include <cuda_runtime.h>
#include <math.h>
#include <stdint.h>

// Problem constants
#define BATCH 32
#define NTOK  784
#define DIM   512
#define NH    8
#define HD    64
#define HH    28
#define WW    28
#define DA    49

typedef unsigned long long u64;

// -------- scratch (__device__ globals; no allocations allowed) --------
// head-planar activations: [b][h][n][d]
__device__ float    g_qh[BATCH * NH * NTOK * HD];
__device__ float    g_k [BATCH * NH * NTOK * HD];
__device__ float    g_v [BATCH * NH * NTOK * HD];
__device__ float    g_pos_bias[NH * DA * NTOK];        // [h,a,n]
__device__ float    g_agent_bias_t[NH * DA * NTOK];    // [h,a,n]
__device__ uint32_t g_xt   [BATCH * NTOK * DIM];
__device__ uint32_t g_qkvw_t[3 * DIM * DIM];           // q_w then kv_w [1536][512]
__device__ uint32_t g_pw_t [DIM * DIM];
__device__ uint32_t g_attn_t[BATCH * NTOK * DIM];      // tf32 attn+dwc (proj input)

__device__ __forceinline__ uint32_t f2tf(float f) {
    uint32_t u;
    asm("cvt.rna.tf32.f32 %0, %1;" : "=r"(u) : "f"(f));
    return u;
}
__device__ __forceinline__ void fma2(u64& d, u64 a, u64 b) {
    asm("fma.rn.f32x2 %0, %1, %2, %0;" : "+l"(d) : "l"(a), "l"(b));
}
__device__ __forceinline__ void mul2(u64& d, u64 a, u64 b) {
    asm("mul.rn.f32x2 %0, %1, %2;" : "=l"(d) : "l"(a), "l"(b));
}
__device__ __forceinline__ float2 unpack2(u64 v) {
    float2 f;
    asm("mov.b64 {%0,%1}, %2;" : "=f"(f.x), "=f"(f.y) : "l"(v));
    return f;
}
__device__ __forceinline__ u64 pack2(float lo, float hi) {
    u64 r;
    asm("mov.b64 %0, {%1,%2};" : "=l"(r) : "f"(lo), "f"(hi));
    return r;
}

// ======================= fp32 -> tf32 conversion (all operands, one kernel) =======================
__global__ void cvt_all(const float4* __restrict__ x, const float4* __restrict__ qw,
                        const float4* __restrict__ kvw, const float4* __restrict__ pw)
{
    const float4* src;
    uint4* dst;
    int n4;
    switch (blockIdx.y) {
        case 0: src = x;   dst = (uint4*)g_xt;                 n4 = BATCH * NTOK * DIM / 4; break;
        case 1: src = qw;  dst = (uint4*)g_qkvw_t;             n4 = DIM * DIM / 4;          break;
        case 2: src = kvw; dst = (uint4*)(g_qkvw_t + DIM*DIM); n4 = 2 * DIM * DIM / 4;      break;
        default: src = pw; dst = (uint4*)g_pw_t;               n4 = DIM * DIM / 4;          break;
    }
    for (int i = blockIdx.x * blockDim.x + threadIdx.x; i < n4; i += gridDim.x * blockDim.x) {
        float4 v = src[i];
        uint4 o;
        o.x = f2tf(v.x); o.y = f2tf(v.y); o.z = f2tf(v.z); o.w = f2tf(v.w);
        dst[i] = o;
    }
}

// ======================= TF32 tensor-core GEMM, cp.async 4-stage =======================
#define GSTAGES 4
#define STAGE_ELEMS (2 * 128 * 20)
#define GEMM_SMEM_BYTES (GSTAGES * STAGE_ELEMS * 4)   // 81920

__device__ __forceinline__ void cp_async16(uint32_t saddr, const void* gptr) {
    asm volatile("cp.async.cg.shared.global [%0], [%1], 16;" :: "r"(saddr), "l"(gptr));
}
__device__ __forceinline__ void cp_commit() {
    asm volatile("cp.async.commit_group;");
}
template<int N> __device__ __forceinline__ void cp_wait() {
    asm volatile("cp.async.wait_group %0;" :: "n"(N));
}

__device__ __forceinline__ void mma_tf32(float* d, const uint32_t* a, const uint32_t* b) {
    asm volatile(
        "mma.sync.aligned.m16n8k8.row.col.f32.tf32.tf32.f32 "
        "{%0,%1,%2,%3}, {%4,%5,%6,%7}, {%8,%9}, {%0,%1,%2,%3};"
        : "+f"(d[0]), "+f"(d[1]), "+f"(d[2]), "+f"(d[3])
        : "r"(a[0]), "r"(a[1]), "r"(a[2]), "r"(a[3]), "r"(b[0]), "r"(b[1]));
}

__device__ __forceinline__ void tf32_gemm_main(const uint32_t* __restrict__ A,
                                               const uint32_t* __restrict__ W,
                                               int K, float acc[4][4][4])
{
    extern __shared__ uint32_t dsm[];
    const int row0 = blockIdx.y * 128;
    const int col0 = blockIdx.x * 128;
    const int tid  = threadIdx.x;
    const int lane = tid & 31;
    const int warp = tid >> 5;
    const int wm = warp >> 2;
    const int wn = warp & 3;
    const int gid = lane >> 2;
    const int tig = lane & 3;

    const int lr = tid >> 1;
    const int lc = (tid & 1) * 8;

    const uint32_t* Ag = A + (size_t)(row0 + lr) * K + lc;
    const uint32_t* Wg = W + (size_t)(col0 + lr) * K + lc;

    uint32_t smem_base = (uint32_t)__cvta_generic_to_shared(dsm);
    const uint32_t a_dst = smem_base + (uint32_t)(lr * 20 + lc) * 4;
    const uint32_t b_dst = a_dst + 128 * 20 * 4;

    const int NITER = K >> 4;

#pragma unroll
    for (int i = 0; i < 4; i++)
#pragma unroll
        for (int j = 0; j < 4; j++)
#pragma unroll
            for (int r = 0; r < 4; r++) acc[i][j][r] = 0.f;

#pragma unroll
    for (int s = 0; s < GSTAGES - 1; s++) {
        uint32_t so = (uint32_t)(s * STAGE_ELEMS) * 4;
        cp_async16(a_dst + so,      Ag + s * 16);
        cp_async16(a_dst + so + 16, Ag + s * 16 + 4);
        cp_async16(b_dst + so,      Wg + s * 16);
        cp_async16(b_dst + so + 16, Wg + s * 16 + 4);
        cp_commit();
    }

    for (int it = 0; it < NITER; it++) {
        cp_wait<GSTAGES - 2>();
        __syncthreads();

        int nxt = it + GSTAGES - 1;
        if (nxt < NITER) {
            int s = nxt & (GSTAGES - 1);
            uint32_t so = (uint32_t)(s * STAGE_ELEMS) * 4;
            cp_async16(a_dst + so,      Ag + nxt * 16);
            cp_async16(a_dst + so + 16, Ag + nxt * 16 + 4);
            cp_async16(b_dst + so,      Wg + nxt * 16);
            cp_async16(b_dst + so + 16, Wg + nxt * 16 + 4);
        }
        cp_commit();

        const uint32_t* As = dsm + (it & (GSTAGES - 1)) * STAGE_ELEMS;
        const uint32_t* Bs = As + 128 * 20;

#pragma unroll
        for (int kk = 0; kk < 16; kk += 8) {
            uint32_t af[4][4], bf[4][2];
#pragma unroll
            for (int mt = 0; mt < 4; mt++) {
                int r = wm * 64 + mt * 16 + gid;
                af[mt][0] = As[r * 20 + kk + tig];
                af[mt][1] = As[(r + 8) * 20 + kk + tig];
                af[mt][2] = As[r * 20 + kk + tig + 4];
                af[mt][3] = As[(r + 8) * 20 + kk + tig + 4];
            }
#pragma unroll
            for (int nt = 0; nt < 4; nt++) {
                int cb = wn * 32 + nt * 8 + gid;
                bf[nt][0] = Bs[cb * 20 + kk + tig];
                bf[nt][1] = Bs[cb * 20 + kk + tig + 4];
            }
#pragma unroll
            for (int mt = 0; mt < 4; mt++)
#pragma unroll
                for (int nt = 0; nt < 4; nt++)
                    mma_tf32(acc[mt][nt], af[mt], bf[nt]);
        }
    }
}

// merged QKV GEMM; epilogue scatters into head-planar [b][h][n][d] arrays.
__global__ void __launch_bounds__(256, 2) gemm_qkv()
{
    float acc[4][4][4];
    tf32_gemm_main(g_xt, g_qkvw_t, DIM, acc);

    const int row0 = blockIdx.y * 128;
    const int col0 = blockIdx.x * 128;
    const int tid  = threadIdx.x;
    const int lane = tid & 31;
    const int warp = tid >> 5;
    const int wm = warp >> 2, wn = warp & 3;
    const int gid = lane >> 2, tig = lane & 3;

    const int seg = col0 >> 9;                 // 0=q,1=k,2=v
    float* P = (seg == 0) ? g_qh : (seg == 1) ? g_k : g_v;
    const int cseg = col0 & 511;

#pragma unroll
    for (int mt = 0; mt < 4; mt++) {
        int r  = row0 + wm * 64 + mt * 16 + gid;
        int bb = r / NTOK, nn = r % NTOK;
        int r8 = r + 8;
        int bb8 = r8 / NTOK, nn8 = r8 % NTOK;
#pragma unroll
        for (int nt = 0; nt < 4; nt++) {
            int c = cseg + wn * 32 + nt * 8 + 2 * tig;
            int h = c >> 6, d = c & 63;
            *(float2*)&P[(((size_t)(bb * NH + h)) * NTOK + nn) * HD + d] =
                make_float2(acc[mt][nt][0], acc[mt][nt][1]);
            *(float2*)&P[(((size_t)(bb8 * NH + h)) * NTOK + nn8) * HD + d] =
                make_float2(acc[mt][nt][2], acc[mt][nt][3]);
        }
    }
}

__global__ void __launch_bounds__(256, 2) gemm_proj(const float* __restrict__ bias,
                                                    float* __restrict__ out)
{
    float acc[4][4][4];
    tf32_gemm_main(g_attn_t, g_pw_t, DIM, acc);

    const int row0 = blockIdx.y * 128;
    const int col0 = blockIdx.x * 128;
    const int tid  = threadIdx.x;
    const int lane = tid & 31;
    const int warp = tid >> 5;
    const int wm = warp >> 2, wn = warp & 3;
    const int gid = lane >> 2, tig = lane & 3;

#pragma unroll
    for (int mt = 0; mt < 4; mt++) {
        int r = row0 + wm * 64 + mt * 16 + gid;
#pragma unroll
        for (int nt = 0; nt < 4; nt++) {
            int c = col0 + wn * 32 + nt * 8 + 2 * tig;
            float2 bb = *(const float2*)&bias[c];
            *(float2*)&out[(size_t)r * DIM + c] =
                make_float2(acc[mt][nt][0] + bb.x, acc[mt][nt][1] + bb.y);
            *(float2*)&out[(size_t)(r + 8) * DIM + c] =
                make_float2(acc[mt][nt][2] + bb.x, acc[mt][nt][3] + bb.y);
        }
    }
}

// ======================= bias precompute =======================
__device__ __forceinline__ float bilin7(const float* __restrict__ t, int i, int j)
{
    float si = (i - 1.5f) * 0.25f;
    float sj = (j - 1.5f) * 0.25f;
    float fi = floorf(si), fj = floorf(sj);
    int i0 = (int)fi, j0 = (int)fj;
    float wi = si - fi, wj = sj - fj;
    int i0c = max(0, min(6, i0)), i1c = max(0, min(6, i0 + 1));
    int j0c = max(0, min(6, j0)), j1c = max(0, min(6, j0 + 1));
    float v00 = t[i0c * 7 + j0c], v01 = t[i0c * 7 + j1c];
    float v10 = t[i1c * 7 + j0c], v11 = t[i1c * 7 + j1c];
    return (1.f - wi) * ((1.f - wj) * v00 + wj * v01)
         +        wi  * ((1.f - wj) * v10 + wj * v11);
}

__global__ void build_bias(const float* __restrict__ an_bias, const float* __restrict__ na_bias,
                           const float* __restrict__ ah_bias, const float* __restrict__ aw_bias,
                           const float* __restrict__ ha_bias, const float* __restrict__ wa_bias)
{
    int ha = blockIdx.x;
    int h = ha / DA, a = ha % DA;
    int n = threadIdx.x;
    int i = n / WW, j = n % WW;
    g_pos_bias[(size_t)ha * NTOK + n] =
        bilin7(an_bias + (size_t)ha * 49, i, j) + ah_bias[ha * HH + i] + aw_bias[ha * WW + j];
    g_agent_bias_t[(size_t)ha * NTOK + n] =
        bilin7(na_bias + (size_t)ha * 49, i, j)
        + ha_bias[(h * HH + i) * DA + a] + wa_bias[(h * WW + j) * DA + a];
}

// ======================= fused attention (pool + both attentions + dwc) =======================
// one block per (b,h), 512 threads = 16 warps.
// dyn smem: sSt[784][49] + sAg[49][68] + sAV[49][68] + sW[9][64] + sWb[64]
#define AG_PITCH 68
#define FA_SMEM_FLOATS (NTOK * DA + 2 * DA * AG_PITCH + 9 * HD + HD)
#define FA_SMEM_BYTES (FA_SMEM_FLOATS * 4)   // 182880

// S^T[n][a] = plane[n][d] . sAg[a][d]  via mma m16n8k8 tf32 (row.col)
__device__ __forceinline__ void score_phase(const float* __restrict__ pl,
                                            float* __restrict__ sSt,
                                            const float* __restrict__ sAg,
                                            int warp, int gid, int tig)
{
    for (int t = warp; t < 49; t += 16) {               // 49 m-tiles of 16 tokens
        int m0 = t * 16;
        uint32_t af[8][4];
        const float* r0 = pl + (size_t)(m0 + gid) * HD;
        const float* r1 = r0 + 8 * HD;
#pragma unroll
        for (int c = 0; c < 8; c++) {
            af[c][0] = f2tf(r0[8 * c + tig]);
            af[c][1] = f2tf(r1[8 * c + tig]);
            af[c][2] = f2tf(r0[8 * c + tig + 4]);
            af[c][3] = f2tf(r1[8 * c + tig + 4]);
        }
#pragma unroll
        for (int j = 0; j < 7; j++) {                   // 7 n-tiles of 8 agents (49 -> pad 56)
            int n0 = j * 8;
            const float* agr = sAg + min(n0 + gid, DA - 1) * AG_PITCH;
            float acc[4] = {0.f, 0.f, 0.f, 0.f};
#pragma unroll
            for (int c = 0; c < 8; c++) {
                uint32_t bf[2];
                bf[0] = f2tf(agr[8 * c + tig]);
                bf[1] = f2tf(agr[8 * c + tig + 4]);
                mma_tf32(acc, af[c], bf);
            }
            int a0 = n0 + 2 * tig;
            float* s0 = sSt + (m0 + gid) * DA;
            float* s1 = s0 + 8 * DA;
            if (a0 < DA)     { s0[a0]     = acc[0]; s1[a0]     = acc[2]; }
            if (a0 + 1 < DA) { s0[a0 + 1] = acc[1]; s1[a0 + 1] = acc[3]; }
        }
    }
}

__global__ void __launch_bounds__(512, 1) fused_attn(const float* __restrict__ dwc_w,
                                                     const float* __restrict__ dwc_b)
{
    extern __shared__ float sm[];
    float* sSt = sm;                          // [784][49]
    float* sAg = sm + NTOK * DA;              // [49][68]
    float* sAV = sAg + DA * AG_PITCH;         // [49][68]
    float* sW  = sAV + DA * AG_PITCH;         // [9][64]
    float* sWb = sW + 9 * HD;                 // [64]
    __shared__ float sInv[DA];
    const int h = blockIdx.x, b = blockIdx.y;
    const int tid = threadIdx.x;
    const int warp = tid >> 5, lane = tid & 31;
    const int gid = lane >> 2, tig = lane & 3;

    const float* qpl = g_qh + ((size_t)(b * NH + h)) * NTOK * HD;
    const float* kpl = g_k  + ((size_t)(b * NH + h)) * NTOK * HD;
    const float* vpl = g_v  + ((size_t)(b * NH + h)) * NTOK * HD;

    // ---- P0: pooled agent (4x4 avg over q image) * 1/8 scale; stage dwc weights ----
    for (int i = tid; i < DA * HD; i += 512) {
        int a = i >> 6, d = i & 63;
        int ai = a / 7, aj = a % 7;
        const float* qb = qpl + ((ai * 4) * WW + aj * 4) * HD + d;
        float s = 0.f;
#pragma unroll
        for (int di = 0; di < 4; di++)
#pragma unroll
            for (int dj = 0; dj < 4; dj++)
                s += qb[(di * WW + dj) * HD];
        sAg[a * AG_PITCH + d] = s * 0.0078125f;   // (1/16)*(1/8)
    }
    for (int i = tid; i < 9 * HD; i += 512)
        sW[i] = dwc_w[(h * HD + (i & 63)) * 9 + (i >> 6)];
    if (tid < HD) sWb[tid] = dwc_b[h * HD + tid];
    __syncthreads();

    // ---- P1: agent scores via mma: sSt[n][a] = k[n].ag[a] ----
    score_phase(kpl, sSt, sAg, warp, gid, tig);
    __syncthreads();

    // ---- P2: softmax over n per agent (bias folded) ----
    for (int a = warp; a < DA; a += 16) {
        const float* pb = g_pos_bias + ((size_t)h * DA + a) * NTOK;
        float m = -1e30f;
        for (int n = lane; n < NTOK; n += 32) m = fmaxf(m, sSt[n * DA + a] + pb[n]);
#pragma unroll
        for (int off = 16; off > 0; off >>= 1) m = fmaxf(m, __shfl_xor_sync(0xffffffffu, m, off));
        float s = 0.f;
        for (int n = lane; n < NTOK; n += 32) {
            float e = __expf(sSt[n * DA + a] + pb[n] - m);
            sSt[n * DA + a] = e; s += e;
        }
#pragma unroll
        for (int off = 16; off > 0; off >>= 1) s += __shfl_xor_sync(0xffffffffu, s, off);
        if (lane == 0) sInv[a] = 1.f / s;
    }
    __syncthreads();

    // ---- P3: agent_v -> sAV (warp owns a = warp+16i; lane owns d-pair) ----
    {
        u64 acc[4];
#pragma unroll
        for (int i = 0; i < 4; i++) acc[i] = 0;
        const u64* vb = (const u64*)vpl + lane;
#pragma unroll 4
        for (int n = 0; n < NTOK; n++) {
            u64 vv = vb[n * 32];
#pragma unroll
            for (int i = 0; i < 4; i++) {
                int a = warp + 16 * i;
                if (a < DA) {
                    float p = sSt[n * DA + a];
                    fma2(acc[i], pack2(p, p), vv);
                }
            }
        }
#pragma unroll
        for (int i = 0; i < 4; i++) {
            int a = warp + 16 * i;
            if (a < DA) {
                float2 f = unpack2(acc[i]);
                float iv = sInv[a];
                *(float2*)&sAV[a * AG_PITCH + 2 * lane] = make_float2(f.x * iv, f.y * iv);
            }
        }
    }
    __syncthreads();

    // ---- P4: q scores via mma (q scale folded in sAg) ----
    score_phase(qpl, sSt, sAg, warp, gid, tig);
    __syncthreads();

    // ---- P5/P6: per-token softmax over a, O = P@AV, dwc, tf32 store ----
    for (int n = tid; n < NTOK; n += 512) {
        float* prow = sSt + n * DA;
        const float* abT = g_agent_bias_t + (size_t)h * DA * NTOK + n;
        float m = -1e30f;
        for (int a = 0; a < DA; a++) m = fmaxf(m, prow[a] + abT[a * NTOK]);
        float sum = 0.f;
        for (int a = 0; a < DA; a++) {
            float e = __expf(prow[a] + abT[a * NTOK] - m);
            prow[a] = e; sum += e;
        }
        float inv = 1.f / sum;
        u64 iv2 = pack2(inv, inv);

        u64 o[32];
#pragma unroll
        for (int k = 0; k < 32; k++) o[k] = 0;
        for (int a = 0; a < DA; a++) {
            float p = prow[a];
            u64 pp = pack2(p, p);
            const u64* Vr = (const u64*)&sAV[a * AG_PITCH];
#pragma unroll
            for (int k = 0; k < 32; k++) fma2(o[k], pp, Vr[k]);
        }
#pragma unroll
        for (int k = 0; k < 32; k++) mul2(o[k], o[k], iv2);

        // depthwise 3x3 on v plane
        int ii = n / WW, jj = n % WW;
#pragma unroll
        for (int di = -1; di <= 1; di++) {
            int y = ii + di;
            if (y < 0 || y >= HH) continue;
#pragma unroll
            for (int dj = -1; dj <= 1; dj++) {
                int xx = jj + dj;
                if (xx < 0 || xx >= WW) continue;
                const u64* vr = (const u64*)(vpl + (size_t)(y * WW + xx) * HD);
                const u64* wr = (const u64*)(sW + ((di + 1) * 3 + (dj + 1)) * HD);
#pragma unroll
                for (int k = 0; k < 32; k++) fma2(o[k], wr[k], vr[k]);
            }
        }

        uint32_t* op = (uint32_t*)(g_attn_t + ((size_t)(b * NTOK + n)) * DIM + h * HD);
#pragma unroll
        for (int k = 0; k < 32; k++) {
            float2 f = unpack2(o[k]);
            op[2 * k]     = f2tf(f.x + sWb[2 * k]);
            op[2 * k + 1] = f2tf(f.y + sWb[2 * k + 1]);
        }
    }
}

// ======================= launch =======================
extern "C" void kernel_launch(void* const* d_in, const int* in_sizes, int n_in,
                              void* d_out, int out_size)
{
    const float* x       = (const float*)d_in[0];
    const float* q_w     = (const float*)d_in[1];
    const float* kv_w    = (const float*)d_in[2];
    const float* proj_w  = (const float*)d_in[3];
    const float* proj_b  = (const float*)d_in[4];
    const float* dwc_w   = (const float*)d_in[5];
    const float* dwc_b   = (const float*)d_in[6];
    const float* an_bias = (const float*)d_in[7];
    const float* na_bias = (const float*)d_in[8];
    const float* ah_bias = (const float*)d_in[9];
    const float* aw_bias = (const float*)d_in[10];
    const float* ha_bias = (const float*)d_in[11];
    const float* wa_bias = (const float*)d_in[12];
    float* out = (float*)d_out;

    cudaFuncSetAttribute(gemm_qkv,   cudaFuncAttributeMaxDynamicSharedMemorySize, GEMM_SMEM_BYTES);
    cudaFuncSetAttribute(gemm_proj,  cudaFuncAttributeMaxDynamicSharedMemorySize, GEMM_SMEM_BYTES);
    cudaFuncSetAttribute(fused_attn, cudaFuncAttributeMaxDynamicSharedMemorySize, FA_SMEM_BYTES);

    // 1: convert operands to tf32
    cvt_all<<<dim3(512, 4), 256>>>((const float4*)x, (const float4*)q_w,
                                   (const float4*)kv_w, (const float4*)proj_w);
    // 2: merged QKV GEMM (head-planar epilogue)
    gemm_qkv<<<dim3(3 * DIM / 128, (BATCH * NTOK) / 128), 256, GEMM_SMEM_BYTES>>>();
    // 3: bias tables
    build_bias<<<NH * DA, NTOK>>>(an_bias, na_bias, ah_bias, aw_bias, ha_bias, wa_bias);
    // 4: fused attention (+dwc)  <-- ncu-profiled slot
    fused_attn<<<dim3(NH, BATCH), 512, FA_SMEM_BYTES>>>(dwc_w, dwc_b);
    // 5: output projection
    gemm_proj<<<dim3(DIM / 128, (BATCH * NTOK) / 128), 256, GEMM_SMEM_BYTES>>>(proj_b, out);
}